// round 13
// baseline (speedup 1.0000x reference)
#include <cuda_runtime.h>
#include <cuda.h>
#include <cuda_fp16.h>
#include <cstdint>

#define M_DIM 4096
#define N_DIM 4096
#define K_DIM 4096

// Scratch (__device__ globals: allocation-free rule)
__device__ __half g_fqw[(size_t)N_DIM * K_DIM];   // fake-quantized W, fp16
__device__ __half g_xh [(size_t)M_DIM * K_DIM];   // x, fp16

// ---------------------------------------------------------------------------
// Fused preprocess kernel (proven round 6).
// ---------------------------------------------------------------------------
__global__ void __launch_bounds__(256)
preprocess_kernel(const float4* __restrict__ W4, const float4* __restrict__ X4)
{
    const int bid = blockIdx.x;
    if (bid & 1) {
        const size_t i = (size_t)(bid >> 1) * 256 + threadIdx.x;
        float4 a = X4[i * 2];
        float4 b = X4[i * 2 + 1];
        __half2 h[4];
        h[0] = __floats2half2_rn(a.x, a.y);
        h[1] = __floats2half2_rn(a.z, a.w);
        h[2] = __floats2half2_rn(b.x, b.y);
        h[3] = __floats2half2_rn(b.z, b.w);
        reinterpret_cast<uint4*>(g_xh)[i] = *reinterpret_cast<uint4*>(h);
        return;
    }

    const int gw   = (bid >> 1) * 8 + (threadIdx.x >> 5);
    const int lane = threadIdx.x & 31;
    const size_t b4 = (size_t)gw * 64 + lane * 2;

    float4 v0 = W4[b4];
    float4 v1 = W4[b4 + 1];

    float mn = fminf(fminf(fminf(v0.x, v0.y), fminf(v0.z, v0.w)),
                     fminf(fminf(v1.x, v1.y), fminf(v1.z, v1.w)));
    float mx = fmaxf(fmaxf(fmaxf(v0.x, v0.y), fmaxf(v0.z, v0.w)),
                     fmaxf(fmaxf(v1.x, v1.y), fmaxf(v1.z, v1.w)));
    mn = fminf(mn, __shfl_xor_sync(0xFFFFFFFFu, mn, 1));
    mn = fminf(mn, __shfl_xor_sync(0xFFFFFFFFu, mn, 2));
    mx = fmaxf(mx, __shfl_xor_sync(0xFFFFFFFFu, mx, 1));
    mx = fmaxf(mx, __shfl_xor_sync(0xFFFFFFFFu, mx, 2));
    mn = fminf(mn, 0.0f);
    mx = fmaxf(mx, 0.0f);

    float sr = __fdiv_rn(fmaxf(mx - mn, 1e-8f), 15.0f);

    float smin = sr, smax = sr;
    #pragma unroll
    for (int o = 4; o < 32; o <<= 1) {
        smin = fminf(smin, __shfl_xor_sync(0xFFFFFFFFu, smin, o));
        smax = fmaxf(smax, __shfl_xor_sync(0xFFFFFFFFu, smax, o));
    }
    const float srange = fmaxf(smax - smin, 1e-8f);
    float si = fminf(fmaxf(rintf(__fdiv_rn(sr - smin, srange) * 63.0f), 0.0f), 63.0f);
    float sq = __fdiv_rn(si, 63.0f) * srange + smin;
    float sb = fmaxf(sq, 1e-8f);
    float inv = __fdiv_rn(1.0f, sb);

    auto dq = [&](float w) -> float {
        float q = fminf(fmaxf(rintf((w - mn) * inv), 0.0f), 15.0f);
        return q * sb + mn;
    };
    __half2 h[4];
    h[0] = __floats2half2_rn(dq(v0.x), dq(v0.y));
    h[1] = __floats2half2_rn(dq(v0.z), dq(v0.w));
    h[2] = __floats2half2_rn(dq(v1.x), dq(v1.y));
    h[3] = __floats2half2_rn(dq(v1.z), dq(v1.w));
    reinterpret_cast<uint4*>(g_fqw)[(size_t)gw * 32 + lane] = *reinterpret_cast<uint4*>(h);
}

// ---------------------------------------------------------------------------
// fp16 GEMM, warp-split-K over 128x64 tiles with R10's proven sync protocol.
// 256 threads: warps 0-3 compute k-step 2l, warps 4-7 k-step 2l+1, each as a
// 2x2 grid of 64x32 warp tiles. A SUPER-STAGE holds both k-slices
// [A(2l) | B(2l) | A(2l+1) | B(2l+1)] = 48KB; 2 super-stages, single
// producer (tid 0), one full-mbarrier per super-stage, one __syncthreads
// per iteration. TMA loads, m16n8k16 HMMA, 2 CTAs/SM. 2048 tiles -> 6.92
// waves (tail ~1% vs 13.5% at BN=128).
// ---------------------------------------------------------------------------
#define BM 128
#define BN 64
#define BK 64
#define A_BYTES 16384                    // 128 rows * 128 B
#define B_BYTES 8192                     // 64 rows * 128 B
#define HALF_STAGE (A_BYTES + B_BYTES)   // 24576 (one k-step)
#define SUPER_BYTES (2 * HALF_STAGE)     // 49152 (two k-steps)
#define NSUPER 2
#define MBAR_BYTES 64
#define SMEM_TOTAL (NSUPER * SUPER_BYTES + MBAR_BYTES)   // 98368
#define NL (K_DIM / BK / 2)              // 32 loop iterations
#define SWZ(o) ((o) ^ (((o) >> 3) & 0x70))
#define RED_STRIDE 66                    // padded fp32 row for epilogue

#define LDSM_X4(r0, r1, r2, r3, a) \
    asm volatile("ldmatrix.sync.aligned.m8n8.x4.shared.b16 {%0,%1,%2,%3}, [%4];" \
                 : "=r"(r0), "=r"(r1), "=r"(r2), "=r"(r3) : "r"(a))

#define MBARRIER_INIT(addr, cnt) \
    asm volatile("mbarrier.init.shared.b64 [%0], %1;" :: "r"(addr), "r"(cnt) : "memory")
#define MBARRIER_EXPECT_TX(addr, bytes) \
    asm volatile("mbarrier.arrive.expect_tx.shared.b64 _, [%0], %1;" :: "r"(addr), "r"(bytes) : "memory")
#define MBARRIER_WAIT_PARITY(addr, par) do {                                        \
    uint32_t _m = (addr); uint32_t _p = (par); uint32_t _done;                      \
    asm volatile("{\n\t.reg .pred p;\n\t"                                           \
        "mbarrier.try_wait.parity.acquire.cta.shared::cta.b64 p, [%1], %2;\n\t"     \
        "selp.b32 %0, 1, 0, p;\n\t}" : "=r"(_done) : "r"(_m), "r"(_p) : "memory");  \
    if (!_done) {                                                                   \
        asm volatile("{\n\t.reg .pred P1;\n\t"                                      \
            "WL_%=:\n\t"                                                            \
            "mbarrier.try_wait.parity.acquire.cta.shared::cta.b64 P1, [%0], %1, 0x989680;\n\t" \
            "@P1 bra.uni WD_%=;\n\t"                                                \
            "bra.uni WL_%=;\n\t"                                                    \
            "WD_%=:\n\t}" :: "r"(_m), "r"(_p) : "memory");                          \
    }                                                                               \
} while (0)
#define TMA_LOAD_2D(sm, tmap, cx, cy, mbar) \
    asm volatile("cp.async.bulk.tensor.2d.shared::cta.global.tile.mbarrier::complete_tx::bytes " \
                 "[%0], [%1, {%2, %3}], [%4];" \
                 :: "r"(sm), "l"(tmap), "r"(cx), "r"(cy), "r"(mbar) : "memory")

__global__ void __launch_bounds__(256, 2)
gemm_fp16_kernel(const __grid_constant__ CUtensorMap tma_a,
                 const __grid_constant__ CUtensorMap tma_b,
                 const float* __restrict__ bias, float* __restrict__ C)
{
    extern __shared__ __align__(1024) char smem[];
    const uint32_t sbase   = (uint32_t)__cvta_generic_to_shared(smem);
    const uint32_t mb_full = sbase + NSUPER * SUPER_BYTES;   // 2 x 8B

    const int tid   = threadIdx.x;
    const int warp  = tid >> 5;
    const int lane  = tid & 31;
    const int group = warp >> 2;        // 0: k-step 2l, 1: k-step 2l+1
    const int wl    = warp & 3;
    const int gid   = lane >> 2;
    const int tig   = lane & 3;

    // rasterization: GROUP_M=8 over grid 32(bm) x 64(bn)
    const int GRID_N  = N_DIM / BN;     // 64
    const int GROUP_M = 8;
    const int gsz = GROUP_M * GRID_N;   // 512
    int tile = blockIdx.x;
    int grp  = tile / gsz;
    int inb  = tile - grp * gsz;
    int bm   = grp * GROUP_M + (inb % GROUP_M);
    int bn   = inb / GROUP_M;

    if (tid == 0) {
        MBARRIER_INIT(mb_full,     1);
        MBARRIER_INIT(mb_full + 8, 1);
    }
    __syncthreads();

    // issue super-stage l: both k-slices 2l and 2l+1 into stage l&1
    auto issue_super = [&](int l) {
        int s = l & 1;
        MBARRIER_EXPECT_TX(mb_full + s * 8, SUPER_BYTES);
        uint32_t sa = sbase + s * SUPER_BYTES;
        int k0 = 2 * l * BK;
        TMA_LOAD_2D(sa,                        &tma_a, k0,      bm * BM, mb_full + s * 8);
        TMA_LOAD_2D(sa + A_BYTES,              &tma_b, k0,      bn * BN, mb_full + s * 8);
        TMA_LOAD_2D(sa + HALF_STAGE,           &tma_a, k0 + BK, bm * BM, mb_full + s * 8);
        TMA_LOAD_2D(sa + HALF_STAGE + A_BYTES, &tma_b, k0 + BK, bn * BN, mb_full + s * 8);
    };

    if (tid == 0) issue_super(0);

    const int wm = (wl >> 1) * 64;
    const int wn = (wl & 1)  * 32;
    const int a_row_base = wm + (lane & 15);
    const int a_col_base = (lane >> 4) << 4;
    const int b_row_base = wn + (lane & 7) + ((lane & 16) >> 1);
    const int b_col_base = (lane & 8) << 1;

    float acc[4][4][4];
    #pragma unroll
    for (int i = 0; i < 4; i++)
        #pragma unroll
        for (int j = 0; j < 4; j++)
            #pragma unroll
            for (int r = 0; r < 4; r++) acc[i][j][r] = 0.0f;

    for (int l = 0; l < NL; ++l) {
        // refill: super l+1 targets stage (l+1)&1, consumed at l-1 and
        // protected by the end-of-iteration __syncthreads (R10 invariant).
        if (tid == 0 && l + 1 < NL) issue_super(l + 1);

        MBARRIER_WAIT_PARITY(mb_full + (l & 1) * 8, (l >> 1) & 1);

        const uint32_t base = sbase + (l & 1) * SUPER_BYTES + group * HALF_STAGE;
        const uint32_t aB = base;
        const uint32_t bB = base + A_BYTES;

        #pragma unroll
        for (int ks = 0; ks < 4; ++ks) {
            const int kb = ks * 32;
            uint32_t af[4][4], bf[4][2];
            #pragma unroll
            for (int mt = 0; mt < 4; ++mt) {
                uint32_t off = (a_row_base + mt * 16) * 128 + kb + a_col_base;
                LDSM_X4(af[mt][0], af[mt][1], af[mt][2], af[mt][3], aB + SWZ(off));
            }
            #pragma unroll
            for (int nt2 = 0; nt2 < 2; ++nt2) {
                uint32_t off = (b_row_base + nt2 * 16) * 128 + kb + b_col_base;
                uint32_t r0, r1, r2, r3;
                LDSM_X4(r0, r1, r2, r3, bB + SWZ(off));
                bf[nt2 * 2][0]     = r0; bf[nt2 * 2][1]     = r1;
                bf[nt2 * 2 + 1][0] = r2; bf[nt2 * 2 + 1][1] = r3;
            }
            #pragma unroll
            for (int mt = 0; mt < 4; ++mt)
                #pragma unroll
                for (int nt = 0; nt < 4; ++nt) {
                    asm volatile(
                        "mma.sync.aligned.m16n8k16.row.col.f32.f16.f16.f32 "
                        "{%0,%1,%2,%3}, {%4,%5,%6,%7}, {%8,%9}, {%0,%1,%2,%3};"
                        : "+f"(acc[mt][nt][0]), "+f"(acc[mt][nt][1]),
                          "+f"(acc[mt][nt][2]), "+f"(acc[mt][nt][3])
                        : "r"(af[mt][0]), "r"(af[mt][1]), "r"(af[mt][2]), "r"(af[mt][3]),
                          "r"(bf[nt][0]), "r"(bf[nt][1]));
                }
        }
        __syncthreads();   // all warps done reading stage l&1
    }

    // ---- epilogue: group 0 -> smem, group 1 adds + bias -> C ----
    float* red = reinterpret_cast<float*>(smem);     // 128 x RED_STRIDE fp32
    if (group == 0) {
        #pragma unroll
        for (int nt = 0; nt < 4; ++nt) {
            int n = wn + nt * 8 + tig * 2;
            #pragma unroll
            for (int mt = 0; mt < 4; ++mt) {
                int m = wm + mt * 16 + gid;
                *reinterpret_cast<float2*>(&red[m * RED_STRIDE + n]) =
                    make_float2(acc[mt][nt][0], acc[mt][nt][1]);
                *reinterpret_cast<float2*>(&red[(m + 8) * RED_STRIDE + n]) =
                    make_float2(acc[mt][nt][2], acc[mt][nt][3]);
            }
        }
    }
    __syncthreads();
    if (group == 1) {
        #pragma unroll
        for (int nt = 0; nt < 4; ++nt) {
            int n = wn + nt * 8 + tig * 2;
            int ng = bn * BN + n;
            float b0 = __ldg(bias + ng), b1 = __ldg(bias + ng + 1);
            #pragma unroll
            for (int mt = 0; mt < 4; ++mt) {
                int m = wm + mt * 16 + gid;
                float2 p0 = *reinterpret_cast<float2*>(&red[m * RED_STRIDE + n]);
                float2 p1 = *reinterpret_cast<float2*>(&red[(m + 8) * RED_STRIDE + n]);
                int mg = bm * BM + m;
                *reinterpret_cast<float2*>(C + (size_t)mg * N_DIM + ng) =
                    make_float2(acc[mt][nt][0] + p0.x + b0, acc[mt][nt][1] + p0.y + b1);
                *reinterpret_cast<float2*>(C + (size_t)(mg + 8) * N_DIM + ng) =
                    make_float2(acc[mt][nt][2] + p1.x + b0, acc[mt][nt][3] + p1.y + b1);
            }
        }
    }
}

// ---------------------------------------------------------------------------
// Host
// ---------------------------------------------------------------------------
typedef CUresult (*PFN_encodeTiled)(CUtensorMap*, CUtensorMapDataType, cuuint32_t, void*,
                                    const cuuint64_t*, const cuuint64_t*, const cuuint32_t*,
                                    const cuuint32_t*, CUtensorMapInterleave, CUtensorMapSwizzle,
                                    CUtensorMapL2promotion, CUtensorMapFloatOOBfill);

extern "C" void kernel_launch(void* const* d_in, const int* in_sizes, int n_in,
                              void* d_out, int out_size)
{
    const float* x    = (const float*)d_in[0];
    const float* w    = (const float*)d_in[1];
    const float* bias = (const float*)d_in[2];
    float* out = (float*)d_out;

    preprocess_kernel<<<16384, 256>>>((const float4*)w, (const float4*)x);

    void* pxh = nullptr; void* pfw = nullptr;
    cudaGetSymbolAddress(&pxh, g_xh);
    cudaGetSymbolAddress(&pfw, g_fqw);

    PFN_encodeTiled enc = nullptr;
    {
        cudaDriverEntryPointQueryResult qr;
#if CUDART_VERSION >= 12050
        cudaGetDriverEntryPointByVersion("cuTensorMapEncodeTiled", (void**)&enc, 12000,
                                         cudaEnableDefault, &qr);
#else
        cudaGetDriverEntryPoint("cuTensorMapEncodeTiled", (void**)&enc, cudaEnableDefault, &qr);
#endif
    }

    alignas(64) CUtensorMap ta, tb;
    cuuint64_t dims[2]    = {K_DIM, M_DIM};
    cuuint64_t strides[1] = {K_DIM * 2};
    cuuint32_t es[2]      = {1, 1};
    cuuint32_t boxA[2]    = {BK, BM};               // 64 halves x 128 rows
    cuuint32_t boxB[2]    = {BK, BN};               // 64 halves x 64 rows

    enc(&ta, CU_TENSOR_MAP_DATA_TYPE_FLOAT16, 2, pxh, dims, strides, boxA, es,
        CU_TENSOR_MAP_INTERLEAVE_NONE, CU_TENSOR_MAP_SWIZZLE_128B,
        CU_TENSOR_MAP_L2_PROMOTION_L2_128B, CU_TENSOR_MAP_FLOAT_OOB_FILL_NONE);
    enc(&tb, CU_TENSOR_MAP_DATA_TYPE_FLOAT16, 2, pfw, dims, strides, boxB, es,
        CU_TENSOR_MAP_INTERLEAVE_NONE, CU_TENSOR_MAP_SWIZZLE_128B,
        CU_TENSOR_MAP_L2_PROMOTION_L2_128B, CU_TENSOR_MAP_FLOAT_OOB_FILL_NONE);

    cudaFuncSetAttribute(gemm_fp16_kernel,
                         cudaFuncAttributeMaxDynamicSharedMemorySize, SMEM_TOTAL);
    const int grid = (M_DIM / BM) * (N_DIM / BN);   // 2048
    gemm_fp16_kernel<<<grid, 256, SMEM_TOTAL>>>(ta, tb, bias, out);
}

// round 14
// speedup vs baseline: 1.0739x; 1.0739x over previous
#include <cuda_runtime.h>
#include <cuda.h>
#include <cuda_fp16.h>
#include <cstdint>

#define M_DIM 4096
#define N_DIM 4096
#define K_DIM 4096

// Scratch (__device__ globals: allocation-free rule)
__device__ __half g_fqw[(size_t)N_DIM * K_DIM];   // fake-quantized W, fp16
__device__ __half g_xh [(size_t)M_DIM * K_DIM];   // x, fp16

// ---------------------------------------------------------------------------
// Fused preprocess kernel (proven round 6).
// ---------------------------------------------------------------------------
__global__ void __launch_bounds__(256)
preprocess_kernel(const float4* __restrict__ W4, const float4* __restrict__ X4)
{
    const int bid = blockIdx.x;
    if (bid & 1) {
        const size_t i = (size_t)(bid >> 1) * 256 + threadIdx.x;
        float4 a = X4[i * 2];
        float4 b = X4[i * 2 + 1];
        __half2 h[4];
        h[0] = __floats2half2_rn(a.x, a.y);
        h[1] = __floats2half2_rn(a.z, a.w);
        h[2] = __floats2half2_rn(b.x, b.y);
        h[3] = __floats2half2_rn(b.z, b.w);
        reinterpret_cast<uint4*>(g_xh)[i] = *reinterpret_cast<uint4*>(h);
        return;
    }

    const int gw   = (bid >> 1) * 8 + (threadIdx.x >> 5);
    const int lane = threadIdx.x & 31;
    const size_t b4 = (size_t)gw * 64 + lane * 2;

    float4 v0 = W4[b4];
    float4 v1 = W4[b4 + 1];

    float mn = fminf(fminf(fminf(v0.x, v0.y), fminf(v0.z, v0.w)),
                     fminf(fminf(v1.x, v1.y), fminf(v1.z, v1.w)));
    float mx = fmaxf(fmaxf(fmaxf(v0.x, v0.y), fmaxf(v0.z, v0.w)),
                     fmaxf(fmaxf(v1.x, v1.y), fmaxf(v1.z, v1.w)));
    mn = fminf(mn, __shfl_xor_sync(0xFFFFFFFFu, mn, 1));
    mn = fminf(mn, __shfl_xor_sync(0xFFFFFFFFu, mn, 2));
    mx = fmaxf(mx, __shfl_xor_sync(0xFFFFFFFFu, mx, 1));
    mx = fmaxf(mx, __shfl_xor_sync(0xFFFFFFFFu, mx, 2));
    mn = fminf(mn, 0.0f);
    mx = fmaxf(mx, 0.0f);

    float sr = __fdiv_rn(fmaxf(mx - mn, 1e-8f), 15.0f);

    float smin = sr, smax = sr;
    #pragma unroll
    for (int o = 4; o < 32; o <<= 1) {
        smin = fminf(smin, __shfl_xor_sync(0xFFFFFFFFu, smin, o));
        smax = fmaxf(smax, __shfl_xor_sync(0xFFFFFFFFu, smax, o));
    }
    const float srange = fmaxf(smax - smin, 1e-8f);
    float si = fminf(fmaxf(rintf(__fdiv_rn(sr - smin, srange) * 63.0f), 0.0f), 63.0f);
    float sq = __fdiv_rn(si, 63.0f) * srange + smin;
    float sb = fmaxf(sq, 1e-8f);
    float inv = __fdiv_rn(1.0f, sb);

    auto dq = [&](float w) -> float {
        float q = fminf(fmaxf(rintf((w - mn) * inv), 0.0f), 15.0f);
        return q * sb + mn;
    };
    __half2 h[4];
    h[0] = __floats2half2_rn(dq(v0.x), dq(v0.y));
    h[1] = __floats2half2_rn(dq(v0.z), dq(v0.w));
    h[2] = __floats2half2_rn(dq(v1.x), dq(v1.y));
    h[3] = __floats2half2_rn(dq(v1.z), dq(v1.w));
    reinterpret_cast<uint4*>(g_fqw)[(size_t)gw * 32 + lane] = *reinterpret_cast<uint4*>(h);
}

// ---------------------------------------------------------------------------
// Hybrid GEMM:
//  CTAs 0..887   (3 exact full waves): 128x128 tiles, R10 protocol.
//  CTAs 888..1159 (tail wave): 136 tiles 888..1023 split into 2 CTAs each,
//                  128x64 warp-split-K, R13 protocol.
// B tensormap box = 64 rows; the full path issues two B loads (1024B-aligned
// boxes -> bytes identical to one 128-row box). m16n8k16 HMMA, 2 CTAs/SM.
// ---------------------------------------------------------------------------
#define BM 128
#define BN 128
#define BK 64
#define A_BYTES 16384                    // 128 rows * 128 B
#define BH_BYTES 8192                    // 64 rows * 128 B
// full path: 3 stages of (A + 2*BH) = 32KB
#define F_STAGE (A_BYTES + 2 * BH_BYTES)
#define F_STAGES 3
// tail path: 2 super-stages of 2*(A + BH) = 48KB
#define T_HALF (A_BYTES + BH_BYTES)
#define T_SUPER (2 * T_HALF)
#define SMEM_DATA (T_SUPER * 2)          // 98304 (>= F_STAGES*F_STAGE)
#define SMEM_TOTAL (SMEM_DATA + 64)
#define NK (K_DIM / BK)                  // 64
#define NL (NK / 2)                      // 32
#define N_FULL 888                       // 3 * 296
#define SWZ(o) ((o) ^ (((o) >> 3) & 0x70))
#define RED_STRIDE 66

#define LDSM_X4(r0, r1, r2, r3, a) \
    asm volatile("ldmatrix.sync.aligned.m8n8.x4.shared.b16 {%0,%1,%2,%3}, [%4];" \
                 : "=r"(r0), "=r"(r1), "=r"(r2), "=r"(r3) : "r"(a))

#define MBARRIER_INIT(addr, cnt) \
    asm volatile("mbarrier.init.shared.b64 [%0], %1;" :: "r"(addr), "r"(cnt) : "memory")
#define MBARRIER_EXPECT_TX(addr, bytes) \
    asm volatile("mbarrier.arrive.expect_tx.shared.b64 _, [%0], %1;" :: "r"(addr), "r"(bytes) : "memory")
#define MBARRIER_WAIT_PARITY(addr, par) do {                                        \
    uint32_t _m = (addr); uint32_t _p = (par); uint32_t _done;                      \
    asm volatile("{\n\t.reg .pred p;\n\t"                                           \
        "mbarrier.try_wait.parity.acquire.cta.shared::cta.b64 p, [%1], %2;\n\t"     \
        "selp.b32 %0, 1, 0, p;\n\t}" : "=r"(_done) : "r"(_m), "r"(_p) : "memory");  \
    if (!_done) {                                                                   \
        asm volatile("{\n\t.reg .pred P1;\n\t"                                      \
            "WL_%=:\n\t"                                                            \
            "mbarrier.try_wait.parity.acquire.cta.shared::cta.b64 P1, [%0], %1, 0x989680;\n\t" \
            "@P1 bra.uni WD_%=;\n\t"                                                \
            "bra.uni WL_%=;\n\t"                                                    \
            "WD_%=:\n\t}" :: "r"(_m), "r"(_p) : "memory");                          \
    }                                                                               \
} while (0)
#define TMA_LOAD_2D(sm, tmap, cx, cy, mbar) \
    asm volatile("cp.async.bulk.tensor.2d.shared::cta.global.tile.mbarrier::complete_tx::bytes " \
                 "[%0], [%1, {%2, %3}], [%4];" \
                 :: "r"(sm), "l"(tmap), "r"(cx), "r"(cy), "r"(mbar) : "memory")

__global__ void __launch_bounds__(256, 2)
gemm_fp16_kernel(const __grid_constant__ CUtensorMap tma_a,
                 const __grid_constant__ CUtensorMap tma_b,
                 const float* __restrict__ bias, float* __restrict__ C)
{
    extern __shared__ __align__(1024) char smem[];
    const uint32_t sbase = (uint32_t)__cvta_generic_to_shared(smem);
    const uint32_t mbar  = sbase + SMEM_DATA;

    const int tid  = threadIdx.x;
    const int warp = tid >> 5;
    const int lane = tid & 31;
    const int gid  = lane >> 2;
    const int tig  = lane & 3;
    const int bid  = blockIdx.x;

    const bool tail = (bid >= N_FULL);
    int t, h;
    if (!tail) { t = bid; h = 0; }
    else       { t = N_FULL + ((bid - N_FULL) >> 1); h = (bid - N_FULL) & 1; }

    // raster t -> (bm, bn) over 32x32 tiles, GROUP_M=8
    const int gsz = 8 * 32;
    int grp = t / gsz;
    int inb = t - grp * gsz;
    int bm  = grp * 8 + (inb & 7);
    int bn  = inb >> 3;

    if (!tail) {
        // ================= FULL PATH (R10 protocol, 128x128) =================
        if (tid == 0) {
            #pragma unroll
            for (int s = 0; s < F_STAGES; s++) MBARRIER_INIT(mbar + s * 8, 1);
        }
        __syncthreads();

        auto issue_stage = [&](int s, int it) {
            MBARRIER_EXPECT_TX(mbar + s * 8, F_STAGE);
            uint32_t sa = sbase + s * F_STAGE;
            TMA_LOAD_2D(sa,                      &tma_a, it * BK, bm * BM,      mbar + s * 8);
            TMA_LOAD_2D(sa + A_BYTES,            &tma_b, it * BK, bn * BN,      mbar + s * 8);
            TMA_LOAD_2D(sa + A_BYTES + BH_BYTES, &tma_b, it * BK, bn * BN + 64, mbar + s * 8);
        };

        if (tid == 0) { issue_stage(0, 0); issue_stage(1, 1); }

        const int wm = (warp >> 2) * 64;
        const int wn = (warp & 3)  * 32;
        const int a_row_base = wm + (lane & 15);
        const int a_col_base = (lane >> 4) << 4;
        const int b_row_base = wn + (lane & 7) + ((lane & 16) >> 1);
        const int b_col_base = (lane & 8) << 1;

        float acc[4][4][4];
        #pragma unroll
        for (int i = 0; i < 4; i++)
            #pragma unroll
            for (int j = 0; j < 4; j++)
                #pragma unroll
                for (int r = 0; r < 4; r++) acc[i][j][r] = 0.0f;

        int stg = 0, phase = 0;
        for (int it = 0; it < NK; ++it) {
            if (tid == 0 && it + 2 < NK) {
                int ns = stg + 2; if (ns >= F_STAGES) ns -= F_STAGES;
                issue_stage(ns, it + 2);
            }
            MBARRIER_WAIT_PARITY(mbar + stg * 8, phase);

            const uint32_t aB = sbase + stg * F_STAGE;
            const uint32_t bB = aB + A_BYTES;

            #pragma unroll
            for (int ks = 0; ks < 4; ++ks) {
                const int kb = ks * 32;
                uint32_t af[4][4], bf[4][2];
                #pragma unroll
                for (int mt = 0; mt < 4; ++mt) {
                    uint32_t off = (a_row_base + mt * 16) * 128 + kb + a_col_base;
                    LDSM_X4(af[mt][0], af[mt][1], af[mt][2], af[mt][3], aB + SWZ(off));
                }
                #pragma unroll
                for (int nt2 = 0; nt2 < 2; ++nt2) {
                    uint32_t off = (b_row_base + nt2 * 16) * 128 + kb + b_col_base;
                    uint32_t r0, r1, r2, r3;
                    LDSM_X4(r0, r1, r2, r3, bB + SWZ(off));
                    bf[nt2 * 2][0]     = r0; bf[nt2 * 2][1]     = r1;
                    bf[nt2 * 2 + 1][0] = r2; bf[nt2 * 2 + 1][1] = r3;
                }
                #pragma unroll
                for (int mt = 0; mt < 4; ++mt)
                    #pragma unroll
                    for (int nt = 0; nt < 4; ++nt) {
                        asm volatile(
                            "mma.sync.aligned.m16n8k16.row.col.f32.f16.f16.f32 "
                            "{%0,%1,%2,%3}, {%4,%5,%6,%7}, {%8,%9}, {%0,%1,%2,%3};"
                            : "+f"(acc[mt][nt][0]), "+f"(acc[mt][nt][1]),
                              "+f"(acc[mt][nt][2]), "+f"(acc[mt][nt][3])
                            : "r"(af[mt][0]), "r"(af[mt][1]), "r"(af[mt][2]), "r"(af[mt][3]),
                              "r"(bf[nt][0]), "r"(bf[nt][1]));
                    }
            }
            __syncthreads();
            if (++stg >= F_STAGES) { stg = 0; }
            if (stg == 0 && it >= F_STAGES - 1) {}   // phase handled below
            phase = (((it + 1) / F_STAGES) & 1);
        }

        #pragma unroll
        for (int nt = 0; nt < 4; ++nt) {
            int n = bn * BN + wn + nt * 8 + tig * 2;
            float b0 = bias[n], b1 = bias[n + 1];
            #pragma unroll
            for (int mt = 0; mt < 4; ++mt) {
                int m = bm * BM + wm + mt * 16 + gid;
                *reinterpret_cast<float2*>(C + (size_t)m       * N_DIM + n) =
                    make_float2(acc[mt][nt][0] + b0, acc[mt][nt][1] + b1);
                *reinterpret_cast<float2*>(C + (size_t)(m + 8) * N_DIM + n) =
                    make_float2(acc[mt][nt][2] + b0, acc[mt][nt][3] + b1);
            }
        }
        return;
    }

    // ================= TAIL PATH (R13 protocol, 128x64, split-K) =============
    const int nb = bn * 2 + h;           // 64-wide column block index
    const int group = warp >> 2;
    const int wl    = warp & 3;

    if (tid == 0) {
        MBARRIER_INIT(mbar,     1);
        MBARRIER_INIT(mbar + 8, 1);
    }
    __syncthreads();

    auto issue_super = [&](int l) {
        int s = l & 1;
        MBARRIER_EXPECT_TX(mbar + s * 8, T_SUPER);
        uint32_t sa = sbase + s * T_SUPER;
        int k0 = 2 * l * BK;
        TMA_LOAD_2D(sa,                     &tma_a, k0,      bm * BM, mbar + s * 8);
        TMA_LOAD_2D(sa + A_BYTES,           &tma_b, k0,      nb * 64, mbar + s * 8);
        TMA_LOAD_2D(sa + T_HALF,            &tma_a, k0 + BK, bm * BM, mbar + s * 8);
        TMA_LOAD_2D(sa + T_HALF + A_BYTES,  &tma_b, k0 + BK, nb * 64, mbar + s * 8);
    };

    if (tid == 0) issue_super(0);

    const int wm = (wl >> 1) * 64;
    const int wn = (wl & 1)  * 32;
    const int a_row_base = wm + (lane & 15);
    const int a_col_base = (lane >> 4) << 4;
    const int b_row_base = wn + (lane & 7) + ((lane & 16) >> 1);
    const int b_col_base = (lane & 8) << 1;

    float acc[4][4][4];
    #pragma unroll
    for (int i = 0; i < 4; i++)
        #pragma unroll
        for (int j = 0; j < 4; j++)
            #pragma unroll
            for (int r = 0; r < 4; r++) acc[i][j][r] = 0.0f;

    for (int l = 0; l < NL; ++l) {
        if (tid == 0 && l + 1 < NL) issue_super(l + 1);
        MBARRIER_WAIT_PARITY(mbar + (l & 1) * 8, (l >> 1) & 1);

        const uint32_t base = sbase + (l & 1) * T_SUPER + group * T_HALF;
        const uint32_t aB = base;
        const uint32_t bB = base + A_BYTES;

        #pragma unroll
        for (int ks = 0; ks < 4; ++ks) {
            const int kb = ks * 32;
            uint32_t af[4][4], bf[4][2];
            #pragma unroll
            for (int mt = 0; mt < 4; ++mt) {
                uint32_t off = (a_row_base + mt * 16) * 128 + kb + a_col_base;
                LDSM_X4(af[mt][0], af[mt][1], af[mt][2], af[mt][3], aB + SWZ(off));
            }
            #pragma unroll
            for (int nt2 = 0; nt2 < 2; ++nt2) {
                uint32_t off = (b_row_base + nt2 * 16) * 128 + kb + b_col_base;
                uint32_t r0, r1, r2, r3;
                LDSM_X4(r0, r1, r2, r3, bB + SWZ(off));
                bf[nt2 * 2][0]     = r0; bf[nt2 * 2][1]     = r1;
                bf[nt2 * 2 + 1][0] = r2; bf[nt2 * 2 + 1][1] = r3;
            }
            #pragma unroll
            for (int mt = 0; mt < 4; ++mt)
                #pragma unroll
                for (int nt = 0; nt < 4; ++nt) {
                    asm volatile(
                        "mma.sync.aligned.m16n8k16.row.col.f32.f16.f16.f32 "
                        "{%0,%1,%2,%3}, {%4,%5,%6,%7}, {%8,%9}, {%0,%1,%2,%3};"
                        : "+f"(acc[mt][nt][0]), "+f"(acc[mt][nt][1]),
                          "+f"(acc[mt][nt][2]), "+f"(acc[mt][nt][3])
                        : "r"(af[mt][0]), "r"(af[mt][1]), "r"(af[mt][2]), "r"(af[mt][3]),
                          "r"(bf[nt][0]), "r"(bf[nt][1]));
                }
        }
        __syncthreads();
    }

    float* red = reinterpret_cast<float*>(smem);
    if (group == 0) {
        #pragma unroll
        for (int nt = 0; nt < 4; ++nt) {
            int n = wn + nt * 8 + tig * 2;
            #pragma unroll
            for (int mt = 0; mt < 4; ++mt) {
                int m = wm + mt * 16 + gid;
                *reinterpret_cast<float2*>(&red[m * RED_STRIDE + n]) =
                    make_float2(acc[mt][nt][0], acc[mt][nt][1]);
                *reinterpret_cast<float2*>(&red[(m + 8) * RED_STRIDE + n]) =
                    make_float2(acc[mt][nt][2], acc[mt][nt][3]);
            }
        }
    }
    __syncthreads();
    if (group == 1) {
        #pragma unroll
        for (int nt = 0; nt < 4; ++nt) {
            int n = wn + nt * 8 + tig * 2;
            int ng = nb * 64 + n;
            float b0 = __ldg(bias + ng), b1 = __ldg(bias + ng + 1);
            #pragma unroll
            for (int mt = 0; mt < 4; ++mt) {
                int m = wm + mt * 16 + gid;
                float2 p0 = *reinterpret_cast<float2*>(&red[m * RED_STRIDE + n]);
                float2 p1 = *reinterpret_cast<float2*>(&red[(m + 8) * RED_STRIDE + n]);
                int mg = bm * BM + m;
                *reinterpret_cast<float2*>(C + (size_t)mg * N_DIM + ng) =
                    make_float2(acc[mt][nt][0] + p0.x + b0, acc[mt][nt][1] + p0.y + b1);
                *reinterpret_cast<float2*>(C + (size_t)(mg + 8) * N_DIM + ng) =
                    make_float2(acc[mt][nt][2] + p1.x + b0, acc[mt][nt][3] + p1.y + b1);
            }
        }
    }
}

// ---------------------------------------------------------------------------
// Host
// ---------------------------------------------------------------------------
typedef CUresult (*PFN_encodeTiled)(CUtensorMap*, CUtensorMapDataType, cuuint32_t, void*,
                                    const cuuint64_t*, const cuuint64_t*, const cuuint32_t*,
                                    const cuuint32_t*, CUtensorMapInterleave, CUtensorMapSwizzle,
                                    CUtensorMapL2promotion, CUtensorMapFloatOOBfill);

extern "C" void kernel_launch(void* const* d_in, const int* in_sizes, int n_in,
                              void* d_out, int out_size)
{
    const float* x    = (const float*)d_in[0];
    const float* w    = (const float*)d_in[1];
    const float* bias = (const float*)d_in[2];
    float* out = (float*)d_out;

    preprocess_kernel<<<16384, 256>>>((const float4*)w, (const float4*)x);

    void* pxh = nullptr; void* pfw = nullptr;
    cudaGetSymbolAddress(&pxh, g_xh);
    cudaGetSymbolAddress(&pfw, g_fqw);

    PFN_encodeTiled enc = nullptr;
    {
        cudaDriverEntryPointQueryResult qr;
#if CUDART_VERSION >= 12050
        cudaGetDriverEntryPointByVersion("cuTensorMapEncodeTiled", (void**)&enc, 12000,
                                         cudaEnableDefault, &qr);
#else
        cudaGetDriverEntryPoint("cuTensorMapEncodeTiled", (void**)&enc, cudaEnableDefault, &qr);
#endif
    }

    alignas(64) CUtensorMap ta, tb;
    cuuint64_t dims[2]    = {K_DIM, M_DIM};
    cuuint64_t strides[1] = {K_DIM * 2};
    cuuint32_t es[2]      = {1, 1};
    cuuint32_t boxA[2]    = {BK, BM};               // 64 halves x 128 rows
    cuuint32_t boxB[2]    = {BK, 64};               // 64 halves x 64 rows

    enc(&ta, CU_TENSOR_MAP_DATA_TYPE_FLOAT16, 2, pxh, dims, strides, boxA, es,
        CU_TENSOR_MAP_INTERLEAVE_NONE, CU_TENSOR_MAP_SWIZZLE_128B,
        CU_TENSOR_MAP_L2_PROMOTION_L2_128B, CU_TENSOR_MAP_FLOAT_OOB_FILL_NONE);
    enc(&tb, CU_TENSOR_MAP_DATA_TYPE_FLOAT16, 2, pfw, dims, strides, boxB, es,
        CU_TENSOR_MAP_INTERLEAVE_NONE, CU_TENSOR_MAP_SWIZZLE_128B,
        CU_TENSOR_MAP_L2_PROMOTION_L2_128B, CU_TENSOR_MAP_FLOAT_OOB_FILL_NONE);

    cudaFuncSetAttribute(gemm_fp16_kernel,
                         cudaFuncAttributeMaxDynamicSharedMemorySize, SMEM_TOTAL);
    const int grid = N_FULL + 2 * (1024 - N_FULL);   // 888 + 272 = 1160
    gemm_fp16_kernel<<<grid, 256, SMEM_TOTAL>>>(ta, tb, bias, out);
}